// round 14
// baseline (speedup 1.0000x reference)
#include <cuda_runtime.h>

#define M_ROWS 12288
#define N_COLS 12288
#define D_DIM  128
#define INV_T  (1.0f/0.07f)
#define IDXCAP 128
#define TB     256
#define SCAN_IT ((N_COLS/4)/TB)   // 12 int4 loads per thread

// ---------------------------------------------------------------------------
// ONE kernel: block = anchor row m.
//  Phase 1: front-batch 12 int4 adj loads (the 604MB DRAM stream).
//  Phase 2: matvec xa = x_anchor[m] @ W in the load shadow (R10-proven).
//  Phase 3: extract neighbor indices -> smem (no global scratch at all).
//  Phase 4: scores + softmax + aggregation epilogue; its issue demand
//           (~130K slot-cyc/SM total) rides in the stream's ~530K free
//           slots while sibling CTAs keep DRAM saturated.
// ---------------------------------------------------------------------------
__global__ void __launch_bounds__(TB) fused_kernel(const int4*   __restrict__ adj4,
                                                   const float4* __restrict__ xanchor4,
                                                   const float4* __restrict__ W4,
                                                   const float*  __restrict__ xin,
                                                   float4*       __restrict__ out4) {
    __shared__ int    s_cnt;
    __shared__ float  s_sum;
    __shared__ float4 s_x[D_DIM / 4];        // anchor row (512B)
    __shared__ float4 s_part[8][D_DIM / 4];  // matvec partials / agg partials (4KB)
    __shared__ float4 s_xa[D_DIM / 4];       // xa row (512B)
    __shared__ int    s_idx[IDXCAP];
    __shared__ float  s_val[IDXCAP];

    const int m    = blockIdx.x;
    const int tid  = threadIdx.x;
    const int wid  = tid >> 5;
    const int lane = tid & 31;
    const float4* xin4 = reinterpret_cast<const float4*>(xin);

    if (tid == 0) s_cnt = 0;
    if (tid < 32) s_x[tid] = xanchor4[(size_t)m * 32 + tid];

    // ---- phase 1: adj row, front-batched DRAM loads ----
    const int4* row = adj4 + (size_t)m * (N_COLS / 4);
    int4 v[SCAN_IT];
    #pragma unroll
    for (int it = 0; it < SCAN_IT; it++)
        v[it] = row[it * TB + tid];

    __syncthreads();   // s_x / s_cnt visible; adj loads still in flight

    // ---- phase 2: matvec partials in the load shadow ----
    {
        float4 acc = make_float4(0.f, 0.f, 0.f, 0.f);
        #pragma unroll
        for (int i = 0; i < 16; i++) {
            const int   d  = wid * 16 + i;
            const float xd = reinterpret_cast<const float*>(s_x)[d];  // warp broadcast
            const float4 w = W4[(size_t)d * 32 + lane];               // L1-hot LDG.128
            acc.x += xd * w.x; acc.y += xd * w.y;
            acc.z += xd * w.z; acc.w += xd * w.w;
        }
        s_part[wid][lane] = acc;
    }

    // ---- phase 3: extract neighbor indices into smem ----
    #pragma unroll
    for (int it = 0; it < SCAN_IT; it++) {
        if (v[it].x | v[it].y | v[it].z | v[it].w) {
            int base = (it * TB + tid) * 4;
            if (v[it].x) { int p = atomicAdd(&s_cnt, 1); if (p < IDXCAP) s_idx[p] = base;     }
            if (v[it].y) { int p = atomicAdd(&s_cnt, 1); if (p < IDXCAP) s_idx[p] = base + 1; }
            if (v[it].z) { int p = atomicAdd(&s_cnt, 1); if (p < IDXCAP) s_idx[p] = base + 2; }
            if (v[it].w) { int p = atomicAdd(&s_cnt, 1); if (p < IDXCAP) s_idx[p] = base + 3; }
        }
    }
    // reduce matvec partials -> s_xa  (needs phase-2 stores of all warps)
    __syncthreads();
    if (tid < 32) {
        float4 r = s_part[0][tid];
        #pragma unroll
        for (int dh = 1; dh < 8; dh++) {
            float4 p = s_part[dh][tid];
            r.x += p.x; r.y += p.y; r.z += p.z; r.w += p.w;
        }
        s_xa[tid] = r;
    }
    __syncthreads();

    const int cnt = min(s_cnt, IDXCAP);

    if (cnt == 0) {
        // all-masked row: uniform softmax -> column mean (P ~ 0; correctness only)
        if (tid < D_DIM) {
            float acc = 0.f;
            for (int n = 0; n < N_COLS; n++)
                acc += xin[(size_t)n * D_DIM + tid];
            reinterpret_cast<float*>(out4)[(size_t)m * D_DIM + tid] = acc * (1.0f / N_COLS);
        }
        return;
    }

    // ---- phase 4a: scores (warp per neighbor, k += 8) ----
    const float4 b = s_xa[lane];
    for (int k = wid; k < cnt; k += 8) {
        const float4 a = xin4[(size_t)s_idx[k] * 32 + lane];
        float p = fmaf(a.x, b.x, fmaf(a.y, b.y, fmaf(a.z, b.z, a.w * b.w)));
        #pragma unroll
        for (int o = 16; o; o >>= 1) p += __shfl_xor_sync(0xffffffffu, p, o);
        if (lane == 0) s_val[k] = p;
    }
    __syncthreads();

    // ---- phase 4b: softmax (warp 0); masked terms exp to exactly 0 ----
    if (wid == 0) {
        float mx = -3.0e38f;
        for (int k = lane; k < cnt; k += 32) mx = fmaxf(mx, s_val[k]);
        #pragma unroll
        for (int o = 16; o; o >>= 1) mx = fmaxf(mx, __shfl_xor_sync(0xffffffffu, mx, o));
        float sm = 0.f;
        for (int k = lane; k < cnt; k += 32) {
            float e = __expf((s_val[k] - mx) * INV_T);
            s_val[k] = e;
            sm += e;
        }
        #pragma unroll
        for (int o = 16; o; o >>= 1) sm += __shfl_xor_sync(0xffffffffu, sm, o);
        if (lane == 0) s_sum = sm;
    }
    __syncthreads();

    // ---- phase 4c: aggregation (warp per neighbor, L1-hit float4 reads) ----
    float4 acc = make_float4(0.f, 0.f, 0.f, 0.f);
    for (int k = wid; k < cnt; k += 8) {
        const float  w = s_val[k];
        const float4 a = xin4[(size_t)s_idx[k] * 32 + lane];
        acc.x += w * a.x; acc.y += w * a.y; acc.z += w * a.z; acc.w += w * a.w;
    }
    s_part[wid][lane] = acc;
    __syncthreads();

    if (tid < 32) {
        float4 r = s_part[0][tid];
        #pragma unroll
        for (int dh = 1; dh < 8; dh++) {
            float4 p = s_part[dh][tid];
            r.x += p.x; r.y += p.y; r.z += p.z; r.w += p.w;
        }
        const float inv = 1.0f / s_sum;
        r.x *= inv; r.y *= inv; r.z *= inv; r.w *= inv;
        out4[(size_t)m * 32 + tid] = r;
    }
}

// ---------------------------------------------------------------------------
// inputs: 0=xx_anchor [12288,128] f32, 1=input [12288,128] f32,
//         2=adj [12288,12288] i32,    3=weight [128,128] f32
// output: [12288,128] f32
//
// ONE kernel. Streams never co-scheduled on this harness (R3/R5/R8/R9), but
// intra-kernel phase fusion provably hides compute in the DRAM stream's idle
// issue slots (R10). Global scratch fully eliminated.
// ---------------------------------------------------------------------------
extern "C" void kernel_launch(void* const* d_in, const int* in_sizes, int n_in,
                              void* d_out, int out_size) {
    const float* xx_anchor = (const float*)d_in[0];
    const float* input     = (const float*)d_in[1];
    const int*   adj       = (const int*)  d_in[2];
    const float* weight    = (const float*)d_in[3];

    fused_kernel<<<M_ROWS, TB>>>((const int4*)adj,
                                 (const float4*)xx_anchor,
                                 (const float4*)weight,
                                 input,
                                 (float4*)d_out);
}

// round 15
// speedup vs baseline: 1.2408x; 1.2408x over previous
#include <cuda_runtime.h>

#define M_ROWS 12288
#define N_COLS 12288
#define D_DIM  128
#define INV_T  (1.0f/0.07f)
#define IDXCAP 128
#define SCAN_TB 256
#define SCAN_IT ((N_COLS/4)/SCAN_TB)   // 12 int4 loads per thread
#define AW      8                       // warps per attn block

// static scratch (allocation-free)
__device__ float g_xa[(size_t)M_ROWS * D_DIM];
__device__ int   g_cnt[M_ROWS];
__device__ int   g_idx[(size_t)M_ROWS * IDXCAP];

// ---------------------------------------------------------------------------
// Kernel S+A fused (R10-proven, 98.2us): adjacency stream + matvec riding
// the idle issue slots. Byte-identical to R10. Do not disturb.
// ---------------------------------------------------------------------------
__global__ void __launch_bounds__(SCAN_TB) scan_xw_kernel(const int4*   __restrict__ adj4,
                                                          const float4* __restrict__ xanchor4,
                                                          const float4* __restrict__ W4) {
    __shared__ int    s_cnt;
    __shared__ float4 s_x[D_DIM / 4];        // anchor row (512B)
    __shared__ float4 s_part[8][D_DIM / 4];  // matvec partials (4KB)

    const int m   = blockIdx.x;
    const int tid = threadIdx.x;

    if (tid == 0) s_cnt = 0;
    if (tid < 32) s_x[tid] = xanchor4[(size_t)m * 32 + tid];

    // ---- adj row: front-batched DRAM loads (issue before any compute) ----
    const int4* row = adj4 + (size_t)m * (N_COLS / 4);
    int4 v[SCAN_IT];
    #pragma unroll
    for (int it = 0; it < SCAN_IT; it++)
        v[it] = row[it * SCAN_TB + tid];

    __syncthreads();   // s_x + s_cnt visible; adj loads still in flight

    // ---- matvec partials while adj loads are in flight ----
    {
        const int e4 = tid & 31;
        const int dh = tid >> 5;
        float4 acc = make_float4(0.f, 0.f, 0.f, 0.f);
        #pragma unroll
        for (int i = 0; i < 16; i++) {
            const int   d  = dh * 16 + i;
            const float xd = reinterpret_cast<const float*>(s_x)[d];  // warp broadcast
            const float4 w = W4[(size_t)d * 32 + e4];                 // L1-hot LDG.128
            acc.x += xd * w.x; acc.y += xd * w.y;
            acc.z += xd * w.z; acc.w += xd * w.w;
        }
        s_part[dh][e4] = acc;
    }

    // ---- consume adj bits (scoreboard waits on the DRAM loads here) ----
    int* rowidx = g_idx + (size_t)m * IDXCAP;
    #pragma unroll
    for (int it = 0; it < SCAN_IT; it++) {
        if (v[it].x | v[it].y | v[it].z | v[it].w) {
            int base = (it * SCAN_TB + tid) * 4;
            if (v[it].x) { int p = atomicAdd(&s_cnt, 1); if (p < IDXCAP) rowidx[p] = base;     }
            if (v[it].y) { int p = atomicAdd(&s_cnt, 1); if (p < IDXCAP) rowidx[p] = base + 1; }
            if (v[it].z) { int p = atomicAdd(&s_cnt, 1); if (p < IDXCAP) rowidx[p] = base + 2; }
            if (v[it].w) { int p = atomicAdd(&s_cnt, 1); if (p < IDXCAP) rowidx[p] = base + 3; }
        }
    }
    __syncthreads();

    if (tid == 0) g_cnt[m] = min(s_cnt, IDXCAP);

    // ---- reduce matvec partials, write xa row ----
    if (tid < 32) {
        float4 r = s_part[0][tid];
        #pragma unroll
        for (int dh = 1; dh < 8; dh++) {
            float4 p = s_part[dh][tid];
            r.x += p.x; r.y += p.y; r.z += p.z; r.w += p.w;
        }
        reinterpret_cast<float4*>(g_xa)[(size_t)m * 32 + tid] = r;
    }
}

// ---------------------------------------------------------------------------
// Kernel C v6: ONE-PASS flash-style attn. 8 warps/row, warp w owns
// k = w, w+8, ... Each iter: load row -> dot -> butterfly (sum in ALL lanes)
// -> online (m,l) update -> FMA into register acc. No aggregation pass, no
// idle-warp softmax, one barrier + tiny 8-way exact merge. Rows processed in
// REVERSE so the first wave hits scan_xw's still-L2-hot tail rows.
// ---------------------------------------------------------------------------
__global__ void __launch_bounds__(AW * 32) attn_flash(const float4* __restrict__ xin4,
                                                      float4*       __restrict__ out4) {
    __shared__ int    s_idx[IDXCAP];
    __shared__ float  s_m[AW];
    __shared__ float  s_l[AW];
    __shared__ float4 s_acc[AW][32];

    const int m    = (M_ROWS - 1) - blockIdx.x;   // reverse: hot-L2 rows first
    const int tid  = threadIdx.x;
    const int wid  = tid >> 5;
    const int lane = tid & 31;
    const unsigned FULL = 0xffffffffu;

    if (tid < IDXCAP) s_idx[tid] = g_idx[(size_t)m * IDXCAP + tid];
    const float4 b = reinterpret_cast<const float4*>(g_xa)[(size_t)m * 32 + lane];
    const int cnt = g_cnt[m];
    __syncthreads();

    if (cnt == 0) {
        // all-masked row: uniform softmax -> column mean (P ~ 0)
        if (tid < D_DIM) {
            float acc = 0.f;
            const float* xin = reinterpret_cast<const float*>(xin4);
            for (int n = 0; n < N_COLS; n++)
                acc += xin[(size_t)n * D_DIM + tid];
            reinterpret_cast<float*>(out4)[(size_t)m * D_DIM + tid] = acc * (1.0f / N_COLS);
        }
        return;
    }

    // ---- one pass: score + online softmax + accumulate, per warp ----
    float  mw = -3.0e38f;
    float  lw = 0.f;
    float4 acc = make_float4(0.f, 0.f, 0.f, 0.f);

    for (int k = wid; k < cnt; k += AW) {
        const int    n = s_idx[k];
        const float4 a = xin4[(size_t)n * 32 + lane];
        float p = fmaf(a.x, b.x, fmaf(a.y, b.y, fmaf(a.z, b.z, a.w * b.w)));
        #pragma unroll
        for (int o = 16; o; o >>= 1) p += __shfl_xor_sync(FULL, p, o);  // sum in ALL lanes

        const float mn = fmaxf(mw, p);
        const float s  = __expf((mw - mn) * INV_T);   // 0 on first iter
        const float e  = __expf((p  - mn) * INV_T);
        lw = lw * s + e;
        acc.x = acc.x * s + e * a.x;
        acc.y = acc.y * s + e * a.y;
        acc.z = acc.z * s + e * a.z;
        acc.w = acc.w * s + e * a.w;
        mw = mn;
    }

    if (lane == 0) { s_m[wid] = mw; s_l[wid] = lw; }
    s_acc[wid][lane] = acc;
    __syncthreads();

    // ---- exact 8-way merge (warp 0) ----
    if (wid == 0) {
        float M = -3.0e38f;
        #pragma unroll
        for (int w = 0; w < AW; w++) M = fmaxf(M, s_m[w]);
        float  L = 0.f;
        float4 r = make_float4(0.f, 0.f, 0.f, 0.f);
        #pragma unroll
        for (int w = 0; w < AW; w++) {
            const float sc = __expf((s_m[w] - M) * INV_T);  // empty warp -> exp(-inf)=0
            L += s_l[w] * sc;
            const float4 aw = s_acc[w][lane];
            r.x += sc * aw.x; r.y += sc * aw.y;
            r.z += sc * aw.z; r.w += sc * aw.w;
        }
        const float inv = 1.0f / L;
        r.x *= inv; r.y *= inv; r.z *= inv; r.w *= inv;
        out4[(size_t)m * 32 + lane] = r;
    }
}

// ---------------------------------------------------------------------------
// inputs: 0=xx_anchor [12288,128] f32, 1=input [12288,128] f32,
//         2=adj [12288,12288] i32,    3=weight [128,128] f32
// output: [12288,128] f32
//
// Two serial kernels. Streams never co-schedule here (R3/R5/R8/R9); full
// single-kernel fusion kills the DRAM stream (R14). scan+xw fused (R10),
// attn rebuilt as one-pass online softmax.
// ---------------------------------------------------------------------------
extern "C" void kernel_launch(void* const* d_in, const int* in_sizes, int n_in,
                              void* d_out, int out_size) {
    const float* xx_anchor = (const float*)d_in[0];
    const float* input     = (const float*)d_in[1];
    const int*   adj       = (const int*)  d_in[2];
    const float* weight    = (const float*)d_in[3];

    scan_xw_kernel<<<M_ROWS, SCAN_TB>>>((const int4*)adj,
                                        (const float4*)xx_anchor,
                                        (const float4*)weight);
    attn_flash<<<M_ROWS, AW * 32>>>((const float4*)input, (float4*)d_out);
}